// round 1
// baseline (speedup 1.0000x reference)
#include <cuda_runtime.h>

// EmbeddedGCN: out[b,i,o] = relu( (sum_j adj[b,i,j]*x[b,i,j,:]) @ W[:,o]
//                                 + bias[o] * sum_j adj[b,i,j] )
// where x = concat(sfeats1, sfeats2) along features.
//
// Shapes: B=16, M=128, FE=64 (each half), FTOT=128, FOUT=128.
// Inputs (metadata order): sfeats1 f32 [B,M,M,64], sfeats2 f32 [B,M,M,64],
//                          adjacency f32 [B,M,M], weight f32 [128,128],
//                          bias f32 [128]. Output f32 [B,M,128].

#define BDIM 16
#define MDIM 128
#define FE   64
#define FTOT 128
#define FOUT 128
#define ROWS 8          // (b,i) rows per block
#define NTHREADS 256

// dynamic smem layout (floats):
//   Wsh  [FTOT*FOUT]        = 16384
//   s    [ROWS*FTOT]        =  1024
//   part [NTHREADS*4]       =  1024   (float4 partials, one per thread)
//   adjs [MDIM]             =   128
//   deg  [ROWS]             =     8
#define SMEM_FLOATS (16384 + 1024 + 1024 + 128 + 8)

__device__ __forceinline__ float4 f4add(float4 a, float4 b) {
    a.x += b.x; a.y += b.y; a.z += b.z; a.w += b.w; return a;
}
__device__ __forceinline__ float4 f4fma(float4 acc, float a, float4 v) {
    acc.x = fmaf(a, v.x, acc.x);
    acc.y = fmaf(a, v.y, acc.y);
    acc.z = fmaf(a, v.z, acc.z);
    acc.w = fmaf(a, v.w, acc.w);
    return acc;
}

__global__ __launch_bounds__(NTHREADS, 3)
void gcn_fused_kernel(const float* __restrict__ sf1,
                      const float* __restrict__ sf2,
                      const float* __restrict__ adj,
                      const float* __restrict__ weight,
                      const float* __restrict__ bias,
                      float* __restrict__ out)
{
    extern __shared__ float smem[];
    float*  Wsh  = smem;                       // 16384
    float*  s    = Wsh + FTOT * FOUT;          // 1024
    float4* part = (float4*)(s + ROWS * FTOT); // 256 float4
    float*  adjs = (float*)(part + NTHREADS);  // 128
    float*  deg  = adjs + MDIM;                // 8

    const int tid  = threadIdx.x;
    const int wid  = tid >> 5;
    const int lane = tid & 31;

    const int blk    = blockIdx.x;
    const int tilesI = MDIM / ROWS;            // 16
    const int b      = blk / tilesI;
    const int i0     = (blk % tilesI) * ROWS;

    // ---- stage W into smem (64 KB), vectorized ----
    {
        const float4* Wg4 = (const float4*)weight;
        float4*       Ws4 = (float4*)Wsh;
        #pragma unroll
        for (int k = 0; k < (FTOT * FOUT / 4) / NTHREADS; ++k)
            Ws4[tid + k * NTHREADS] = Wg4[tid + k * NTHREADS];
    }

    // ---- pooling: s[r][f] = sum_j adj[b,i0+r,j] * x[b,i0+r,j,f] ----
    // thread -> (jc = warp id, fg = lane): jc covers j in [jc*16, jc*16+16),
    // fg in [0,16) reads sf1 float4 fg, fg in [16,32) reads sf2 float4 fg-16.
    const int jc = wid;          // 0..7
    const int fg = lane;         // 0..31

    for (int r = 0; r < ROWS; ++r) {
        const int i       = i0 + r;
        const long rowOff = (long)(b * MDIM + i) * MDIM;   // in j units

        // load adjacency row into smem
        if (tid < MDIM) adjs[tid] = adj[rowOff + tid];
        __syncthreads();

        const float4* src = (fg < 16)
            ? (const float4*)sf1 + rowOff * (FE / 4) + fg
            : (const float4*)sf2 + rowOff * (FE / 4) + (fg - 16);

        float4 acc = make_float4(0.f, 0.f, 0.f, 0.f);
        const int jbase = jc * 16;
        #pragma unroll
        for (int jj = 0; jj < 16; ++jj) {
            const int j = jbase + jj;
            const float a = adjs[j];
            const float4 v = __ldg(src + (long)j * (FE / 4));
            acc = f4fma(acc, a, v);
        }
        part[tid] = acc;
        __syncthreads();

        if (wid == 0) {
            // lane t reduces partials for feature-group t across 8 j-chunks
            float4 v = part[lane];
            #pragma unroll
            for (int k = 1; k < 8; ++k) v = f4add(v, part[lane + 32 * k]);
            ((float4*)(s + r * FTOT))[lane] = v;
        } else if (wid == 1) {
            // degree = sum_j adj (for the bias term)
            float d = adjs[lane] + adjs[lane + 32] + adjs[lane + 64] + adjs[lane + 96];
            #pragma unroll
            for (int o = 16; o > 0; o >>= 1)
                d += __shfl_down_sync(0xffffffffu, d, o);
            if (lane == 0) deg[r] = d;
        }
        __syncthreads();
    }

    // ---- tiny GEMM + bias*deg + relu ----
    // warp r computes row r; lane 'og' computes outputs [og*4, og*4+4)
    {
        const int r  = wid;            // 0..7
        const int og = lane;           // 0..31
        const float4* Ws4 = (const float4*)Wsh;
        const float*  sr  = s + r * FTOT;

        float4 acc = make_float4(0.f, 0.f, 0.f, 0.f);
        #pragma unroll
        for (int f = 0; f < FTOT; ++f) {
            const float sv = sr[f];
            acc = f4fma(acc, sv, Ws4[f * (FOUT / 4) + og]);
        }
        const float  d  = deg[r];
        const float4 bb = ((const float4*)bias)[og];
        acc.x = fmaxf(fmaf(bb.x, d, acc.x), 0.f);
        acc.y = fmaxf(fmaf(bb.y, d, acc.y), 0.f);
        acc.z = fmaxf(fmaf(bb.z, d, acc.z), 0.f);
        acc.w = fmaxf(fmaf(bb.w, d, acc.w), 0.f);

        float4* out4 = (float4*)out;
        out4[(long)(b * MDIM + i0 + r) * (FOUT / 4) + og] = acc;
    }
}

extern "C" void kernel_launch(void* const* d_in, const int* in_sizes, int n_in,
                              void* d_out, int out_size)
{
    const float* sf1    = (const float*)d_in[0];
    const float* sf2    = (const float*)d_in[1];
    const float* adj    = (const float*)d_in[2];
    const float* weight = (const float*)d_in[3];
    const float* bias   = (const float*)d_in[4];
    float* out          = (float*)d_out;

    const int smemBytes = SMEM_FLOATS * (int)sizeof(float);
    cudaFuncSetAttribute(gcn_fused_kernel,
                         cudaFuncAttributeMaxDynamicSharedMemorySize, smemBytes);

    const int grid = BDIM * (MDIM / ROWS);   // 16 * 16 = 256 blocks
    gcn_fused_kernel<<<grid, NTHREADS, smemBytes>>>(sf1, sf2, adj, weight, bias, out);
}